// round 2
// baseline (speedup 1.0000x reference)
#include <cuda_runtime.h>
#include <cstdint>

#define NN 100000
#define NE 1600000
#define FF 64
#define F2 (FF/2)

// theta coefficients
#define TH0 0.6f
#define TH1 (-0.4f)
#define TH2 0.3f
#define TH3 (-0.2f)
#define TH4 0.1f

// ---- scratch (static device globals; no runtime allocation) ----
__device__ float g_featA[NN * FF];
__device__ float g_featB[NN * FF];
__device__ int   g_deg[NN];
__device__ int   g_off[NN];
__device__ int   g_cursor[NN];
__device__ float g_dis[NN];
__device__ int   g_srcSorted[NE];   // stores src * (F/2)  (float2 row offset)
__device__ float g_wSorted[NE];     // dis[src]
__device__ int   g_blockSums[256];

// ---------------- preprocessing kernels ----------------

__global__ void k_zero(int n) {
    int i = blockIdx.x * blockDim.x + threadIdx.x;
    if (i < n) { g_deg[i] = 0; g_cursor[i] = 0; }
}

__global__ void k_hist(const int* __restrict__ edge, int e) {
    int i = blockIdx.x * blockDim.x + threadIdx.x;
    if (i < e) {
        int dst = edge[NE + i];  // edge_index[1] block (int32)
        atomicAdd(&g_deg[dst], 1);
    }
}

__global__ void k_dis(int n) {
    int i = blockIdx.x * blockDim.x + threadIdx.x;
    if (i < n) {
        int d = g_deg[i];
        g_dis[i] = rsqrtf((float)(d < 1 ? 1 : d));
    }
}

// exclusive scan of g_deg into g_off  (phase 1: per-1024-block scan)
__global__ void k_scan1(int n) {
    __shared__ int warpSums[32];
    int i = blockIdx.x * 1024 + threadIdx.x;
    int v = (i < n) ? g_deg[i] : 0;
    int lane = threadIdx.x & 31, wid = threadIdx.x >> 5;
    int x = v;
    #pragma unroll
    for (int o = 1; o < 32; o <<= 1) {
        int t = __shfl_up_sync(0xffffffffu, x, o);
        if (lane >= o) x += t;
    }
    if (lane == 31) warpSums[wid] = x;
    __syncthreads();
    if (wid == 0) {
        int s = warpSums[lane];
        #pragma unroll
        for (int o = 1; o < 32; o <<= 1) {
            int t = __shfl_up_sync(0xffffffffu, s, o);
            if (lane >= o) s += t;
        }
        warpSums[lane] = s;
    }
    __syncthreads();
    int prefix = (wid > 0 ? warpSums[wid - 1] : 0) + (x - v);  // exclusive
    if (i < n) g_off[i] = prefix;
    if (threadIdx.x == 1023) g_blockSums[blockIdx.x] = warpSums[31];
}

__global__ void k_scan2(int nb) {
    if (threadIdx.x == 0 && blockIdx.x == 0) {
        int acc = 0;
        for (int b = 0; b < nb; b++) { int t = g_blockSums[b]; g_blockSums[b] = acc; acc += t; }
    }
}

__global__ void k_scan3(int n) {
    int i = blockIdx.x * 1024 + threadIdx.x;
    if (i < n) g_off[i] += g_blockSums[blockIdx.x];
}

__global__ void k_scatter(const int* __restrict__ edge, int e) {
    int i = blockIdx.x * blockDim.x + threadIdx.x;
    if (i < e) {
        int src = edge[i];
        int dst = edge[NE + i];
        int pos = g_off[dst] + atomicAdd(&g_cursor[dst], 1);
        g_srcSorted[pos] = src * F2;      // pre-scaled float2 row base
        g_wSorted[pos]   = g_dis[src];
    }
}

// ---------------- propagation step (warp per node, float2 per lane) ----------------
// STEP selects the ping-pong buffers at compile time so kernel_launch needs no
// cudaGetSymbolAddress. STEP=1: x -> A, 2: A -> B, 3: B -> A, 4: A -> B.

template <int STEP>
__global__ void k_step(const float* __restrict__ xIn,
                       float* __restrict__ hOut,
                       float theta, int n)
{
    int node = (blockIdx.x * blockDim.x + threadIdx.x) >> 5;
    int lane = threadIdx.x & 31;
    if (node >= n) return;

    const float2* __restrict__ fp2 =
        (STEP == 1) ? (const float2*)xIn :
        (STEP == 3) ? (const float2*)g_featB :
                      (const float2*)g_featA;
    float2* __restrict__ fn2 =
        (STEP == 1 || STEP == 3) ? (float2*)g_featA : (float2*)g_featB;

    int beg = g_off[node];
    int cnt = g_deg[node];

    float2 acc = make_float2(0.f, 0.f);
    int e = 0;
    for (; e + 1 < cnt; e += 2) {
        int   s0 = __ldg(&g_srcSorted[beg + e]);
        int   s1 = __ldg(&g_srcSorted[beg + e + 1]);
        float w0 = __ldg(&g_wSorted[beg + e]);
        float w1 = __ldg(&g_wSorted[beg + e + 1]);
        float2 v0 = __ldg(&fp2[s0 + lane]);
        float2 v1 = __ldg(&fp2[s1 + lane]);
        acc.x += w0 * v0.x + w1 * v1.x;
        acc.y += w0 * v0.y + w1 * v1.y;
    }
    if (e < cnt) {
        int   s0 = __ldg(&g_srcSorted[beg + e]);
        float w0 = __ldg(&g_wSorted[beg + e]);
        float2 v0 = __ldg(&fp2[s0 + lane]);
        acc.x += w0 * v0.x;
        acc.y += w0 * v0.y;
    }

    float din = g_dis[node];
    int   idx2 = node * F2 + lane;
    float2 prev = __ldg(&fp2[idx2]);
    float2 out;
    out.x = prev.x - din * acc.x;
    out.y = prev.y - din * acc.y;
    fn2[idx2] = out;

    float2 h;
    if (STEP == 1) {
        // fp2 == x here, so h = TH0*x + theta*out
        h.x = TH0 * prev.x + theta * out.x;
        h.y = TH0 * prev.y + theta * out.y;
    } else {
        h = ((float2*)hOut)[idx2];
        h.x += theta * out.x;
        h.y += theta * out.y;
    }
    ((float2*)hOut)[idx2] = h;
}

// ---------------- launcher ----------------

extern "C" void kernel_launch(void* const* d_in, const int* in_sizes, int n_in,
                              void* d_out, int out_size)
{
    const float* x    = (const float*)d_in[0];   // [N, 64] fp32
    const int*   edge = (const int*)d_in[1];     // [2, E] int32 (JAX x64 disabled)

    const int n = NN, e = NE;
    const int NB_SCAN = (n + 1023) / 1024;   // 98

    float* h = (float*)d_out;

    k_zero<<<(n + 255) / 256, 256>>>(n);
    k_hist<<<(e + 255) / 256, 256>>>(edge, e);
    k_dis<<<(n + 255) / 256, 256>>>(n);
    k_scan1<<<NB_SCAN, 1024>>>(n);
    k_scan2<<<1, 32>>>(NB_SCAN);
    k_scan3<<<NB_SCAN, 1024>>>(n);
    k_scatter<<<(e + 255) / 256, 256>>>(edge, e);

    const int TPB = 256;                       // 8 warps/block
    const int NBLK = (n * 32 + TPB - 1) / TPB; // warp per node

    k_step<1><<<NBLK, TPB>>>(x, h, TH1, n);
    k_step<2><<<NBLK, TPB>>>(x, h, TH2, n);
    k_step<3><<<NBLK, TPB>>>(x, h, TH3, n);
    k_step<4><<<NBLK, TPB>>>(x, h, TH4, n);
}

// round 4
// speedup vs baseline: 1.0947x; 1.0947x over previous
#include <cuda_runtime.h>
#include <cuda_fp16.h>
#include <cstdint>

#define NN 100000
#define NE 1600000
#define FF 64
#define F2 (FF/2)   // float2 lanes
#define H2 (FF/2)   // half2 lanes (32 per row)

#define TH0 0.6f
#define TH1 (-0.4f)
#define TH2 0.3f
#define TH3 (-0.2f)
#define TH4 0.1f

// ---- scratch (static device globals; no runtime allocation) ----
// 5 fp16 feature buffers: f[0] = fp16(x), f[k] = k-th L_sym power applied
__device__ __half g_f16_0[NN * FF];
__device__ __half g_f16_1[NN * FF];
__device__ __half g_f16_2[NN * FF];
__device__ __half g_f16_3[NN * FF];
__device__ __half g_f16_4[NN * FF];
__device__ int    g_deg[NN];
__device__ int    g_off[NN];
__device__ int    g_cursor[NN];
__device__ float  g_dis[NN];
__device__ int2   g_edgeSorted[NE];   // .x = src*32 (half2 row base), .y = bits(dis[src])
__device__ int    g_blockSums[256];

// ---------------- preprocessing ----------------

__global__ void k_zero(int n) {
    int i = blockIdx.x * blockDim.x + threadIdx.x;
    if (i < n) { g_deg[i] = 0; g_cursor[i] = 0; }
}

__global__ void k_hist(const int* __restrict__ edge, int e) {
    int i = blockIdx.x * blockDim.x + threadIdx.x;
    if (i < e) atomicAdd(&g_deg[edge[NE + i]], 1);
}

__global__ void k_dis(int n) {
    int i = blockIdx.x * blockDim.x + threadIdx.x;
    if (i < n) {
        int d = g_deg[i];
        g_dis[i] = rsqrtf((float)(d < 1 ? 1 : d));
    }
}

__global__ void k_scan1(int n) {
    __shared__ int warpSums[32];
    int i = blockIdx.x * 1024 + threadIdx.x;
    int v = (i < n) ? g_deg[i] : 0;
    int lane = threadIdx.x & 31, wid = threadIdx.x >> 5;
    int x = v;
    #pragma unroll
    for (int o = 1; o < 32; o <<= 1) {
        int t = __shfl_up_sync(0xffffffffu, x, o);
        if (lane >= o) x += t;
    }
    if (lane == 31) warpSums[wid] = x;
    __syncthreads();
    if (wid == 0) {
        int s = warpSums[lane];
        #pragma unroll
        for (int o = 1; o < 32; o <<= 1) {
            int t = __shfl_up_sync(0xffffffffu, s, o);
            if (lane >= o) s += t;
        }
        warpSums[lane] = s;
    }
    __syncthreads();
    int prefix = (wid > 0 ? warpSums[wid - 1] : 0) + (x - v);
    if (i < n) g_off[i] = prefix;
    if (threadIdx.x == 1023) g_blockSums[blockIdx.x] = warpSums[31];
}

__global__ void k_scan2(int nb) {
    if (threadIdx.x == 0 && blockIdx.x == 0) {
        int acc = 0;
        for (int b = 0; b < nb; b++) { int t = g_blockSums[b]; g_blockSums[b] = acc; acc += t; }
    }
}

__global__ void k_scan3(int n) {
    int i = blockIdx.x * 1024 + threadIdx.x;
    if (i < n) g_off[i] += g_blockSums[blockIdx.x];
}

__global__ void k_scatter(const int* __restrict__ edge, int e) {
    int i = blockIdx.x * blockDim.x + threadIdx.x;
    if (i < e) {
        int src = edge[i];
        int dst = edge[NE + i];
        int pos = g_off[dst] + atomicAdd(&g_cursor[dst], 1);
        int2 rec;
        rec.x = src * H2;                       // half2 row base
        rec.y = __float_as_int(g_dis[src]);
        g_edgeSorted[pos] = rec;
    }
}

// x fp32 -> f0 fp16
__global__ void k_tohalf(const float* __restrict__ x, int n2) {
    int i = blockIdx.x * blockDim.x + threadIdx.x;
    if (i < n2) {
        float2 v = ((const float2*)x)[i];
        ((__half2*)g_f16_0)[i] = __float22half2_rn(v);
    }
}

// ---------------- propagation step: warp per node, half2 per lane ----------------
// STEP k: gather from f[k-1], write f[k]. All fp32 math, fp16 storage.

template <int STEP>
__global__ void k_step(int n) {
    int node = (blockIdx.x * blockDim.x + threadIdx.x) >> 5;
    int lane = threadIdx.x & 31;
    if (node >= n) return;

    const __half2* __restrict__ fp =
        (STEP == 1) ? (const __half2*)g_f16_0 :
        (STEP == 2) ? (const __half2*)g_f16_1 :
        (STEP == 3) ? (const __half2*)g_f16_2 :
                      (const __half2*)g_f16_3;
    __half2* __restrict__ fn =
        (STEP == 1) ? (__half2*)g_f16_1 :
        (STEP == 2) ? (__half2*)g_f16_2 :
        (STEP == 3) ? (__half2*)g_f16_3 :
                      (__half2*)g_f16_4;

    int beg = g_off[node];
    int cnt = g_deg[node];

    const int2* __restrict__ es = (const int2*)g_edgeSorted;

    float2 acc = make_float2(0.f, 0.f);
    int e = 0;
    for (; e + 1 < cnt; e += 2) {
        int2 r0 = __ldg(&es[beg + e]);
        int2 r1 = __ldg(&es[beg + e + 1]);
        float2 v0 = __half22float2(__ldg(&fp[r0.x + lane]));
        float2 v1 = __half22float2(__ldg(&fp[r1.x + lane]));
        float w0 = __int_as_float(r0.y);
        float w1 = __int_as_float(r1.y);
        acc.x += w0 * v0.x + w1 * v1.x;
        acc.y += w0 * v0.y + w1 * v1.y;
    }
    if (e < cnt) {
        int2 r0 = __ldg(&es[beg + e]);
        float2 v0 = __half22float2(__ldg(&fp[r0.x + lane]));
        float w0 = __int_as_float(r0.y);
        acc.x += w0 * v0.x;
        acc.y += w0 * v0.y;
    }

    float din = g_dis[node];
    int idx = node * H2 + lane;
    float2 prev = __half22float2(__ldg(&fp[idx]));
    float2 out;
    out.x = prev.x - din * acc.x;
    out.y = prev.y - din * acc.y;
    fn[idx] = __float22half2_rn(out);
}

// ---------------- final combine: h = th0*x + sum th_k * f_k ----------------

__global__ void k_combine(const float* __restrict__ x, float* __restrict__ h, int n2) {
    int i = blockIdx.x * blockDim.x + threadIdx.x;
    if (i < n2) {
        float2 xv = ((const float2*)x)[i];
        float2 f1 = __half22float2(((const __half2*)g_f16_1)[i]);
        float2 f2 = __half22float2(((const __half2*)g_f16_2)[i]);
        float2 f3 = __half22float2(((const __half2*)g_f16_3)[i]);
        float2 f4 = __half22float2(((const __half2*)g_f16_4)[i]);
        float2 o;
        o.x = TH0 * xv.x + TH1 * f1.x + TH2 * f2.x + TH3 * f3.x + TH4 * f4.x;
        o.y = TH0 * xv.y + TH1 * f1.y + TH2 * f2.y + TH3 * f3.y + TH4 * f4.y;
        ((float2*)h)[i] = o;
    }
}

// ---------------- launcher ----------------

extern "C" void kernel_launch(void* const* d_in, const int* in_sizes, int n_in,
                              void* d_out, int out_size)
{
    const float* x    = (const float*)d_in[0];   // [N, 64] fp32
    const int*   edge = (const int*)d_in[1];     // [2, E] int32

    const int n = NN, e = NE;
    const int n2 = NN * F2;                  // 3.2M float2/half2 elements
    const int NB_SCAN = (n + 1023) / 1024;

    float* h = (float*)d_out;

    k_zero<<<(n + 255) / 256, 256>>>(n);
    k_hist<<<(e + 255) / 256, 256>>>(edge, e);
    k_dis<<<(n + 255) / 256, 256>>>(n);
    k_scan1<<<NB_SCAN, 1024>>>(n);
    k_scan2<<<1, 32>>>(NB_SCAN);
    k_scan3<<<NB_SCAN, 1024>>>(n);
    k_scatter<<<(e + 255) / 256, 256>>>(edge, e);
    k_tohalf<<<(n2 + 255) / 256, 256>>>(x, n2);

    const int TPB = 256;
    const int NBLK = (n * 32 + TPB - 1) / TPB;   // warp per node

    k_step<1><<<NBLK, TPB>>>(n);
    k_step<2><<<NBLK, TPB>>>(n);
    k_step<3><<<NBLK, TPB>>>(n);
    k_step<4><<<NBLK, TPB>>>(n);

    k_combine<<<(n2 + 255) / 256, 256>>>(x, h, n2);
}